// round 10
// baseline (speedup 1.0000x reference)
#include <cuda_runtime.h>

// SSIM loss — R5 kernel, byte-identical structure, two changes only:
//  1) __launch_bounds__(256, 4): force 64 regs -> 4 CTAs/SM (occupancy bet)
//  2) last-block-done reduction (no zeroing kernel)

#define NT      256
#define EXTX    64
#define TILE_X  54
#define TILE_Y  48
#define R       12
#define SVS     65          // row stride in 16B elements (odd -> conflict-free)
#define IMG     512
#define GRIDX   10
#define GRIDY   11
#define NBLK    (GRIDX * GRIDY * 48)

#define KWc0 0.0010283801f
#define KWc1 0.0075987582f
#define KWc2 0.0360007696f
#define KWc3 0.1093606947f
#define KWc4 0.2130055430f
#define KWc5 0.2660117300f

#define C1V 0.0001f
#define C2V 0.0009f

__device__ float    g_sum = 0.0f;
__device__ unsigned g_cnt = 0u;

__device__ __forceinline__ void fma2(float2& d, float2 a, float2 b) {
    asm("fma.rn.f32x2 %0, %1, %2, %0;"
        : "+l"(reinterpret_cast<unsigned long long&>(d))
        : "l"(reinterpret_cast<const unsigned long long&>(a)),
          "l"(reinterpret_cast<const unsigned long long&>(b)));
}

__global__ void __launch_bounds__(NT, 4)
ssim_occ4_kernel(const float* __restrict__ img1,
                 const float* __restrict__ img2,
                 float* __restrict__ out)
{
    float2 wpair[6];
    wpair[0] = make_float2(KWc0, KWc0); wpair[1] = make_float2(KWc1, KWc1);
    wpair[2] = make_float2(KWc2, KWc2); wpair[3] = make_float2(KWc3, KWc3);
    wpair[4] = make_float2(KWc4, KWc4); wpair[5] = make_float2(KWc5, KWc5);
    #define WPK(k) wpair[(k) <= 5 ? (k) : 10 - (k)]

    extern __shared__ float4 sV[];   // [TILE_Y][SVS] : (A,B,P,Q) vertical-filtered

    const int tid  = threadIdx.x;
    const int base = blockIdx.z * (IMG * IMG);
    const int x0   = blockIdx.x * TILE_X;
    const int y0   = blockIdx.y * TILE_Y;

    const bool interior = (x0 >= 5) && (x0 + EXTX - 5 <= IMG) &&
                          (y0 >= 5) && (y0 + TILE_Y + 5 <= IMG);

    // ---------------- Stage V: vertical 11-tap, f32x2 registers ------------
    {
        const int c   = tid & (EXTX - 1);
        const int g   = tid >> 6;            // row group 0..3
        const int gx  = x0 - 5 + c;
        const int iy0 = y0 + g * R - 5;

        float2 accAB[R], accPQ[R];
        #pragma unroll
        for (int o = 0; o < R; ++o) {
            accAB[o] = make_float2(0.f, 0.f);
            accPQ[o] = make_float2(0.f, 0.f);
        }

        if (interior) {
            const float* p1 = img1 + base + iy0 * IMG + gx;
            const float* p2 = img2 + base + iy0 * IMG + gx;
            #pragma unroll
            for (int j = 0; j < R + 10; ++j) {
                float a = __ldg(p1 + j * IMG);
                float b = __ldg(p2 + j * IMG);
                float2 ab = make_float2(a, b);
                float2 pq = make_float2(a * a + b * b, a * b);
                #pragma unroll
                for (int o = 0; o < R; ++o) {
                    int k = j - o;
                    if (k >= 0 && k <= 10) {
                        fma2(accAB[o], WPK(k), ab);
                        fma2(accPQ[o], WPK(k), pq);
                    }
                }
            }
        } else {
            const bool xok = (unsigned)gx < (unsigned)IMG;
            #pragma unroll
            for (int j = 0; j < R + 10; ++j) {
                int gy = iy0 + j;
                float a = 0.f, b = 0.f;
                if (xok && (unsigned)gy < (unsigned)IMG) {
                    int off = base + gy * IMG + gx;
                    a = __ldg(img1 + off);
                    b = __ldg(img2 + off);
                }
                float2 ab = make_float2(a, b);
                float2 pq = make_float2(a * a + b * b, a * b);
                #pragma unroll
                for (int o = 0; o < R; ++o) {
                    int k = j - o;
                    if (k >= 0 && k <= 10) {
                        fma2(accAB[o], WPK(k), ab);
                        fma2(accPQ[o], WPK(k), pq);
                    }
                }
            }
        }

        #pragma unroll
        for (int o = 0; o < R; ++o)
            sV[(g * R + o) * SVS + c] =
                make_float4(accAB[o].x, accAB[o].y, accPQ[o].x, accPQ[o].y);
    }
    __syncthreads();

    // ------- Stage H: j-streaming horizontal 11-tap + SSIM, 6 cols/task ----
    float loss = 0.0f;
    for (int t = tid; t < 9 * TILE_Y; t += NT) {     // 9 chunks x 48 rows = 432
        int row = t % TILE_Y;
        int c0  = (t / TILE_Y) * 6;

        float2 oAB[6], oPQ[6];
        #pragma unroll
        for (int cc = 0; cc < 6; ++cc) {
            oAB[cc] = make_float2(0.f, 0.f);
            oPQ[cc] = make_float2(0.f, 0.f);
        }

        #pragma unroll
        for (int j = 0; j < 16; ++j) {
            float4 v = sV[row * SVS + c0 + j];
            float2 vab = make_float2(v.x, v.y);
            float2 vpq = make_float2(v.z, v.w);
            #pragma unroll
            for (int cc = 0; cc < 6; ++cc) {
                int k = j - cc;
                if (k >= 0 && k <= 10) {
                    fma2(oAB[cc], WPK(k), vab);
                    fma2(oPQ[cc], WPK(k), vpq);
                }
            }
        }

        int  gy  = y0 + row;
        int  ox0 = x0 + c0;
        bool yok = gy < IMG;

        #pragma unroll
        for (int cc = 0; cc < 6; ++cc) {
            float A = oAB[cc].x, B = oAB[cc].y;
            float P = oPQ[cc].x, Q = oPQ[cc].y;
            float AB   = A * B;
            float AA   = A * A;
            float num1 = 2.0f * AB + C1V;
            float num2 = 2.0f * (Q - AB) + C2V;
            float den1 = fmaf(B, B, C1V) + AA;           // AA+BB+C1
            float den2 = (P - den1) + (C1V + C2V);       // P-AA-BB+C2
            float ssim = __fdividef(num1 * num2, den1 * den2);
            float l    = fmaf(ssim, -0.5f, 0.5f);        // (1-ssim)/2
            l = fminf(fmaxf(l, 0.0f), 0.5f);             // clip (NaN-safe)
            if (yok && (ox0 + cc) < IMG) loss += l;
        }
    }

    // ---------------- Block reduction + last-block finish -------------------
    #pragma unroll
    for (int s = 16; s > 0; s >>= 1)
        loss += __shfl_xor_sync(0xFFFFFFFFu, loss, s);

    __shared__ float warpsum[NT / 32];
    if ((tid & 31) == 0) warpsum[tid >> 5] = loss;
    __syncthreads();
    if (tid == 0) {
        float bsum = 0.f;
        #pragma unroll
        for (int w = 0; w < NT / 32; ++w) bsum += warpsum[w];
        atomicAdd(&g_sum, bsum);
        __threadfence();
        unsigned ticket = atomicAdd(&g_cnt, 1u);
        if (ticket == NBLK - 1) {
            float total = atomicAdd(&g_sum, 0.0f);       // coherent read
            const float inv_total = 1.0f / (16.0f * 3.0f * 512.0f * 512.0f);
            out[0] = total * inv_total;
            g_sum = 0.0f;                                // reset for next replay
            g_cnt = 0u;
        }
    }
}

extern "C" void kernel_launch(void* const* d_in, const int* in_sizes, int n_in,
                              void* d_out, int out_size)
{
    const float* img1 = (const float*)d_in[0];
    const float* img2 = (const float*)d_in[1];
    float* out = (float*)d_out;

    const int smem_bytes = TILE_Y * SVS * (int)sizeof(float4);  // 49920
    cudaFuncSetAttribute(ssim_occ4_kernel,
                         cudaFuncAttributeMaxDynamicSharedMemorySize, smem_bytes);

    dim3 grid(GRIDX, GRIDY, 48);   // 10 x 11 x 48 = 5280 blocks
    ssim_occ4_kernel<<<grid, NT, smem_bytes>>>(img1, img2, out);
}

// round 11
// speedup vs baseline: 1.1686x; 1.1686x over previous
#include <cuda_runtime.h>

// SSIM loss — R5 kernel (best measured: 57.9us kernel, fma 72.5%),
// byte-identical compute structure at __launch_bounds__(256,3),
// plus last-block-done reduction (removes the zeroing kernel launch).

#define NT      256
#define EXTX    64
#define TILE_X  54
#define TILE_Y  48
#define R       12
#define SVS     65          // row stride in 16B elements (odd -> conflict-free)
#define IMG     512
#define GRIDX   10
#define GRIDY   11
#define NBLK    (GRIDX * GRIDY * 48)

#define KWc0 0.0010283801f
#define KWc1 0.0075987582f
#define KWc2 0.0360007696f
#define KWc3 0.1093606947f
#define KWc4 0.2130055430f
#define KWc5 0.2660117300f

#define C1V 0.0001f
#define C2V 0.0009f

__device__ float    g_sum = 0.0f;
__device__ unsigned g_cnt = 0u;

__device__ __forceinline__ void fma2(float2& d, float2 a, float2 b) {
    asm("fma.rn.f32x2 %0, %1, %2, %0;"
        : "+l"(reinterpret_cast<unsigned long long&>(d))
        : "l"(reinterpret_cast<const unsigned long long&>(a)),
          "l"(reinterpret_cast<const unsigned long long&>(b)));
}

__global__ void __launch_bounds__(NT, 3)
ssim_final_kernel(const float* __restrict__ img1,
                  const float* __restrict__ img2,
                  float* __restrict__ out)
{
    float2 wpair[6];
    wpair[0] = make_float2(KWc0, KWc0); wpair[1] = make_float2(KWc1, KWc1);
    wpair[2] = make_float2(KWc2, KWc2); wpair[3] = make_float2(KWc3, KWc3);
    wpair[4] = make_float2(KWc4, KWc4); wpair[5] = make_float2(KWc5, KWc5);
    #define WPK(k) wpair[(k) <= 5 ? (k) : 10 - (k)]

    extern __shared__ float4 sV[];   // [TILE_Y][SVS] : (A,B,P,Q) vertical-filtered

    const int tid  = threadIdx.x;
    const int base = blockIdx.z * (IMG * IMG);
    const int x0   = blockIdx.x * TILE_X;
    const int y0   = blockIdx.y * TILE_Y;

    const bool interior = (x0 >= 5) && (x0 + EXTX - 5 <= IMG) &&
                          (y0 >= 5) && (y0 + TILE_Y + 5 <= IMG);

    // ---------------- Stage V: vertical 11-tap, f32x2 registers ------------
    {
        const int c   = tid & (EXTX - 1);
        const int g   = tid >> 6;            // row group 0..3
        const int gx  = x0 - 5 + c;
        const int iy0 = y0 + g * R - 5;

        float2 accAB[R], accPQ[R];
        #pragma unroll
        for (int o = 0; o < R; ++o) {
            accAB[o] = make_float2(0.f, 0.f);
            accPQ[o] = make_float2(0.f, 0.f);
        }

        if (interior) {
            const float* p1 = img1 + base + iy0 * IMG + gx;
            const float* p2 = img2 + base + iy0 * IMG + gx;
            #pragma unroll
            for (int j = 0; j < R + 10; ++j) {
                float a = __ldg(p1 + j * IMG);
                float b = __ldg(p2 + j * IMG);
                float2 ab = make_float2(a, b);
                float2 pq = make_float2(a * a + b * b, a * b);
                #pragma unroll
                for (int o = 0; o < R; ++o) {
                    int k = j - o;
                    if (k >= 0 && k <= 10) {
                        fma2(accAB[o], WPK(k), ab);
                        fma2(accPQ[o], WPK(k), pq);
                    }
                }
            }
        } else {
            const bool xok = (unsigned)gx < (unsigned)IMG;
            #pragma unroll
            for (int j = 0; j < R + 10; ++j) {
                int gy = iy0 + j;
                float a = 0.f, b = 0.f;
                if (xok && (unsigned)gy < (unsigned)IMG) {
                    int off = base + gy * IMG + gx;
                    a = __ldg(img1 + off);
                    b = __ldg(img2 + off);
                }
                float2 ab = make_float2(a, b);
                float2 pq = make_float2(a * a + b * b, a * b);
                #pragma unroll
                for (int o = 0; o < R; ++o) {
                    int k = j - o;
                    if (k >= 0 && k <= 10) {
                        fma2(accAB[o], WPK(k), ab);
                        fma2(accPQ[o], WPK(k), pq);
                    }
                }
            }
        }

        #pragma unroll
        for (int o = 0; o < R; ++o)
            sV[(g * R + o) * SVS + c] =
                make_float4(accAB[o].x, accAB[o].y, accPQ[o].x, accPQ[o].y);
    }
    __syncthreads();

    // ------- Stage H: j-streaming horizontal 11-tap + SSIM, 6 cols/task ----
    float loss = 0.0f;
    for (int t = tid; t < 9 * TILE_Y; t += NT) {     // 9 chunks x 48 rows = 432
        int row = t % TILE_Y;
        int c0  = (t / TILE_Y) * 6;

        float2 oAB[6], oPQ[6];
        #pragma unroll
        for (int cc = 0; cc < 6; ++cc) {
            oAB[cc] = make_float2(0.f, 0.f);
            oPQ[cc] = make_float2(0.f, 0.f);
        }

        #pragma unroll
        for (int j = 0; j < 16; ++j) {
            float4 v = sV[row * SVS + c0 + j];
            float2 vab = make_float2(v.x, v.y);
            float2 vpq = make_float2(v.z, v.w);
            #pragma unroll
            for (int cc = 0; cc < 6; ++cc) {
                int k = j - cc;
                if (k >= 0 && k <= 10) {
                    fma2(oAB[cc], WPK(k), vab);
                    fma2(oPQ[cc], WPK(k), vpq);
                }
            }
        }

        int  gy  = y0 + row;
        int  ox0 = x0 + c0;
        bool yok = gy < IMG;

        #pragma unroll
        for (int cc = 0; cc < 6; ++cc) {
            float A = oAB[cc].x, B = oAB[cc].y;
            float P = oPQ[cc].x, Q = oPQ[cc].y;
            float AB   = A * B;
            float AA   = A * A;
            float num1 = 2.0f * AB + C1V;
            float num2 = 2.0f * (Q - AB) + C2V;
            float den1 = fmaf(B, B, C1V) + AA;           // AA+BB+C1
            float den2 = (P - den1) + (C1V + C2V);       // P-AA-BB+C2
            float ssim = __fdividef(num1 * num2, den1 * den2);
            float l    = fmaf(ssim, -0.5f, 0.5f);        // (1-ssim)/2
            l = fminf(fmaxf(l, 0.0f), 0.5f);             // clip (NaN-safe)
            if (yok && (ox0 + cc) < IMG) loss += l;
        }
    }

    // ---------------- Block reduction + last-block finish -------------------
    #pragma unroll
    for (int s = 16; s > 0; s >>= 1)
        loss += __shfl_xor_sync(0xFFFFFFFFu, loss, s);

    __shared__ float warpsum[NT / 32];
    if ((tid & 31) == 0) warpsum[tid >> 5] = loss;
    __syncthreads();
    if (tid == 0) {
        float bsum = 0.f;
        #pragma unroll
        for (int w = 0; w < NT / 32; ++w) bsum += warpsum[w];
        atomicAdd(&g_sum, bsum);
        __threadfence();
        unsigned ticket = atomicAdd(&g_cnt, 1u);
        if (ticket == NBLK - 1) {
            float total = atomicAdd(&g_sum, 0.0f);       // coherent read
            const float inv_total = 1.0f / (16.0f * 3.0f * 512.0f * 512.0f);
            out[0] = total * inv_total;
            g_sum = 0.0f;                                // reset for next replay
            g_cnt = 0u;
        }
    }
}

extern "C" void kernel_launch(void* const* d_in, const int* in_sizes, int n_in,
                              void* d_out, int out_size)
{
    const float* img1 = (const float*)d_in[0];
    const float* img2 = (const float*)d_in[1];
    float* out = (float*)d_out;

    const int smem_bytes = TILE_Y * SVS * (int)sizeof(float4);  // 49920
    cudaFuncSetAttribute(ssim_final_kernel,
                         cudaFuncAttributeMaxDynamicSharedMemorySize, smem_bytes);

    dim3 grid(GRIDX, GRIDY, 48);   // 10 x 11 x 48 = 5280 blocks
    ssim_final_kernel<<<grid, NT, smem_bytes>>>(img1, img2, out);
}

// round 12
// speedup vs baseline: 1.1814x; 1.0110x over previous
#include <cuda_runtime.h>

// SSIM loss — R5 compute verbatim (best kernel: 57.9us, fma 72.5%),
// last-block-done finish using release/acquire atomics (NO __threadfence:
// gpu-scope membar costs ~1.3kcyc serialized + L1 flush per block tail,
// measured as a 5.6us kernel regression in R11).

#define NT      256
#define EXTX    64
#define TILE_X  54
#define TILE_Y  48
#define R       12
#define SVS     65          // row stride in 16B elements (odd -> conflict-free)
#define IMG     512
#define GRIDX   10
#define GRIDY   11
#define NBLK    (GRIDX * GRIDY * 48)

#define KWc0 0.0010283801f
#define KWc1 0.0075987582f
#define KWc2 0.0360007696f
#define KWc3 0.1093606947f
#define KWc4 0.2130055430f
#define KWc5 0.2660117300f

#define C1V 0.0001f
#define C2V 0.0009f

__device__ float    g_sum = 0.0f;
__device__ unsigned g_cnt = 0u;

__device__ __forceinline__ void fma2(float2& d, float2 a, float2 b) {
    asm("fma.rn.f32x2 %0, %1, %2, %0;"
        : "+l"(reinterpret_cast<unsigned long long&>(d))
        : "l"(reinterpret_cast<const unsigned long long&>(a)),
          "l"(reinterpret_cast<const unsigned long long&>(b)));
}

__global__ void __launch_bounds__(NT, 3)
ssim_relacq_kernel(const float* __restrict__ img1,
                   const float* __restrict__ img2,
                   float* __restrict__ out)
{
    float2 wpair[6];
    wpair[0] = make_float2(KWc0, KWc0); wpair[1] = make_float2(KWc1, KWc1);
    wpair[2] = make_float2(KWc2, KWc2); wpair[3] = make_float2(KWc3, KWc3);
    wpair[4] = make_float2(KWc4, KWc4); wpair[5] = make_float2(KWc5, KWc5);
    #define WPK(k) wpair[(k) <= 5 ? (k) : 10 - (k)]

    extern __shared__ float4 sV[];   // [TILE_Y][SVS] : (A,B,P,Q) vertical-filtered

    const int tid  = threadIdx.x;
    const int base = blockIdx.z * (IMG * IMG);
    const int x0   = blockIdx.x * TILE_X;
    const int y0   = blockIdx.y * TILE_Y;

    const bool interior = (x0 >= 5) && (x0 + EXTX - 5 <= IMG) &&
                          (y0 >= 5) && (y0 + TILE_Y + 5 <= IMG);

    // ---------------- Stage V: vertical 11-tap, f32x2 registers ------------
    {
        const int c   = tid & (EXTX - 1);
        const int g   = tid >> 6;            // row group 0..3
        const int gx  = x0 - 5 + c;
        const int iy0 = y0 + g * R - 5;

        float2 accAB[R], accPQ[R];
        #pragma unroll
        for (int o = 0; o < R; ++o) {
            accAB[o] = make_float2(0.f, 0.f);
            accPQ[o] = make_float2(0.f, 0.f);
        }

        if (interior) {
            const float* p1 = img1 + base + iy0 * IMG + gx;
            const float* p2 = img2 + base + iy0 * IMG + gx;
            #pragma unroll
            for (int j = 0; j < R + 10; ++j) {
                float a = __ldg(p1 + j * IMG);
                float b = __ldg(p2 + j * IMG);
                float2 ab = make_float2(a, b);
                float2 pq = make_float2(a * a + b * b, a * b);
                #pragma unroll
                for (int o = 0; o < R; ++o) {
                    int k = j - o;
                    if (k >= 0 && k <= 10) {
                        fma2(accAB[o], WPK(k), ab);
                        fma2(accPQ[o], WPK(k), pq);
                    }
                }
            }
        } else {
            const bool xok = (unsigned)gx < (unsigned)IMG;
            #pragma unroll
            for (int j = 0; j < R + 10; ++j) {
                int gy = iy0 + j;
                float a = 0.f, b = 0.f;
                if (xok && (unsigned)gy < (unsigned)IMG) {
                    int off = base + gy * IMG + gx;
                    a = __ldg(img1 + off);
                    b = __ldg(img2 + off);
                }
                float2 ab = make_float2(a, b);
                float2 pq = make_float2(a * a + b * b, a * b);
                #pragma unroll
                for (int o = 0; o < R; ++o) {
                    int k = j - o;
                    if (k >= 0 && k <= 10) {
                        fma2(accAB[o], WPK(k), ab);
                        fma2(accPQ[o], WPK(k), pq);
                    }
                }
            }
        }

        #pragma unroll
        for (int o = 0; o < R; ++o)
            sV[(g * R + o) * SVS + c] =
                make_float4(accAB[o].x, accAB[o].y, accPQ[o].x, accPQ[o].y);
    }
    __syncthreads();

    // ------- Stage H: j-streaming horizontal 11-tap + SSIM, 6 cols/task ----
    float loss = 0.0f;
    for (int t = tid; t < 9 * TILE_Y; t += NT) {     // 9 chunks x 48 rows = 432
        int row = t % TILE_Y;
        int c0  = (t / TILE_Y) * 6;

        float2 oAB[6], oPQ[6];
        #pragma unroll
        for (int cc = 0; cc < 6; ++cc) {
            oAB[cc] = make_float2(0.f, 0.f);
            oPQ[cc] = make_float2(0.f, 0.f);
        }

        #pragma unroll
        for (int j = 0; j < 16; ++j) {
            float4 v = sV[row * SVS + c0 + j];
            float2 vab = make_float2(v.x, v.y);
            float2 vpq = make_float2(v.z, v.w);
            #pragma unroll
            for (int cc = 0; cc < 6; ++cc) {
                int k = j - cc;
                if (k >= 0 && k <= 10) {
                    fma2(oAB[cc], WPK(k), vab);
                    fma2(oPQ[cc], WPK(k), vpq);
                }
            }
        }

        int  gy  = y0 + row;
        int  ox0 = x0 + c0;
        bool yok = gy < IMG;

        #pragma unroll
        for (int cc = 0; cc < 6; ++cc) {
            float A = oAB[cc].x, B = oAB[cc].y;
            float P = oPQ[cc].x, Q = oPQ[cc].y;
            float AB   = A * B;
            float AA   = A * A;
            float num1 = 2.0f * AB + C1V;
            float num2 = 2.0f * (Q - AB) + C2V;
            float den1 = fmaf(B, B, C1V) + AA;           // AA+BB+C1
            float den2 = (P - den1) + (C1V + C2V);       // P-AA-BB+C2
            float ssim = __fdividef(num1 * num2, den1 * den2);
            float l    = fmaf(ssim, -0.5f, 0.5f);        // (1-ssim)/2
            l = fminf(fmaxf(l, 0.0f), 0.5f);             // clip (NaN-safe)
            if (yok && (ox0 + cc) < IMG) loss += l;
        }
    }

    // ---------- Block reduction + release/acquire last-block finish ---------
    #pragma unroll
    for (int s = 16; s > 0; s >>= 1)
        loss += __shfl_xor_sync(0xFFFFFFFFu, loss, s);

    __shared__ float warpsum[NT / 32];
    if ((tid & 31) == 0) warpsum[tid >> 5] = loss;
    __syncthreads();
    if (tid == 0) {
        float bsum = 0.f;
        #pragma unroll
        for (int w = 0; w < NT / 32; ++w) bsum += warpsum[w];

        // fire-and-forget partial accumulate (relaxed, no return)
        asm volatile("red.relaxed.gpu.global.add.f32 [%0], %1;"
                     :: "l"(&g_sum), "f"(bsum) : "memory");
        // ticket with RELEASE: orders the red above without membar/L1 flush
        unsigned ticket;
        asm volatile("atom.release.gpu.global.add.u32 %0, [%1], %2;"
                     : "=r"(ticket) : "l"(&g_cnt), "r"(1u) : "memory");
        if (ticket == NBLK - 1) {
            float total;
            asm volatile("atom.acquire.gpu.global.add.f32 %0, [%1], %2;"
                         : "=f"(total) : "l"(&g_sum), "f"(0.0f) : "memory");
            const float inv_total = 1.0f / (16.0f * 3.0f * 512.0f * 512.0f);
            out[0] = total * inv_total;
            // reset for next graph replay (all blocks done; replays serialized)
            asm volatile("st.global.relaxed.gpu.f32 [%0], %1;"
                         :: "l"(&g_sum), "f"(0.0f) : "memory");
            asm volatile("st.global.relaxed.gpu.u32 [%0], %1;"
                         :: "l"(&g_cnt), "r"(0u) : "memory");
        }
    }
}

extern "C" void kernel_launch(void* const* d_in, const int* in_sizes, int n_in,
                              void* d_out, int out_size)
{
    const float* img1 = (const float*)d_in[0];
    const float* img2 = (const float*)d_in[1];
    float* out = (float*)d_out;

    const int smem_bytes = TILE_Y * SVS * (int)sizeof(float4);  // 49920
    cudaFuncSetAttribute(ssim_relacq_kernel,
                         cudaFuncAttributeMaxDynamicSharedMemorySize, smem_bytes);

    dim3 grid(GRIDX, GRIDY, 48);   // 10 x 11 x 48 = 5280 blocks
    ssim_relacq_kernel<<<grid, NT, smem_bytes>>>(img1, img2, out);
}

// round 13
// speedup vs baseline: 1.2266x; 1.0383x over previous
#include <cuda_runtime.h>

// SSIM loss — R5 compute verbatim. Main kernel ends with a RESULT-DISCARDED
// atomicAdd (ptxas -> REDG fire-and-forget: no block-tail ATOMG round-trip,
// which cost 5.6us / 4.6pp occupancy in R11/R12). A trailing 1-thread
// finisher kernel (stream-ordered after all REDs) scales into out[0] and
// resets the accumulator for the next graph replay.

#define NT      256
#define EXTX    64
#define TILE_X  54
#define TILE_Y  48
#define R       12
#define SVS     65          // row stride in 16B elements (odd -> conflict-free)
#define IMG     512
#define GRIDX   10
#define GRIDY   11

#define KWc0 0.0010283801f
#define KWc1 0.0075987582f
#define KWc2 0.0360007696f
#define KWc3 0.1093606947f
#define KWc4 0.2130055430f
#define KWc5 0.2660117300f

#define C1V 0.0001f
#define C2V 0.0009f

__device__ float g_sum = 0.0f;

__global__ void ssim_finish(float* out) {
    const float inv_total = 1.0f / (16.0f * 3.0f * 512.0f * 512.0f);
    out[0] = g_sum * inv_total;
    g_sum = 0.0f;                      // reset for next graph replay
}

__device__ __forceinline__ void fma2(float2& d, float2 a, float2 b) {
    asm("fma.rn.f32x2 %0, %1, %2, %0;"
        : "+l"(reinterpret_cast<unsigned long long&>(d))
        : "l"(reinterpret_cast<const unsigned long long&>(a)),
          "l"(reinterpret_cast<const unsigned long long&>(b)));
}

__global__ void __launch_bounds__(NT, 3)
ssim_main_kernel(const float* __restrict__ img1,
                 const float* __restrict__ img2)
{
    float2 wpair[6];
    wpair[0] = make_float2(KWc0, KWc0); wpair[1] = make_float2(KWc1, KWc1);
    wpair[2] = make_float2(KWc2, KWc2); wpair[3] = make_float2(KWc3, KWc3);
    wpair[4] = make_float2(KWc4, KWc4); wpair[5] = make_float2(KWc5, KWc5);
    #define WPK(k) wpair[(k) <= 5 ? (k) : 10 - (k)]

    extern __shared__ float4 sV[];   // [TILE_Y][SVS] : (A,B,P,Q) vertical-filtered

    const int tid  = threadIdx.x;
    const int base = blockIdx.z * (IMG * IMG);
    const int x0   = blockIdx.x * TILE_X;
    const int y0   = blockIdx.y * TILE_Y;

    const bool interior = (x0 >= 5) && (x0 + EXTX - 5 <= IMG) &&
                          (y0 >= 5) && (y0 + TILE_Y + 5 <= IMG);

    // ---------------- Stage V: vertical 11-tap, f32x2 registers ------------
    {
        const int c   = tid & (EXTX - 1);
        const int g   = tid >> 6;            // row group 0..3
        const int gx  = x0 - 5 + c;
        const int iy0 = y0 + g * R - 5;

        float2 accAB[R], accPQ[R];
        #pragma unroll
        for (int o = 0; o < R; ++o) {
            accAB[o] = make_float2(0.f, 0.f);
            accPQ[o] = make_float2(0.f, 0.f);
        }

        if (interior) {
            const float* p1 = img1 + base + iy0 * IMG + gx;
            const float* p2 = img2 + base + iy0 * IMG + gx;
            #pragma unroll
            for (int j = 0; j < R + 10; ++j) {
                float a = __ldg(p1 + j * IMG);
                float b = __ldg(p2 + j * IMG);
                float2 ab = make_float2(a, b);
                float2 pq = make_float2(a * a + b * b, a * b);
                #pragma unroll
                for (int o = 0; o < R; ++o) {
                    int k = j - o;
                    if (k >= 0 && k <= 10) {
                        fma2(accAB[o], WPK(k), ab);
                        fma2(accPQ[o], WPK(k), pq);
                    }
                }
            }
        } else {
            const bool xok = (unsigned)gx < (unsigned)IMG;
            #pragma unroll
            for (int j = 0; j < R + 10; ++j) {
                int gy = iy0 + j;
                float a = 0.f, b = 0.f;
                if (xok && (unsigned)gy < (unsigned)IMG) {
                    int off = base + gy * IMG + gx;
                    a = __ldg(img1 + off);
                    b = __ldg(img2 + off);
                }
                float2 ab = make_float2(a, b);
                float2 pq = make_float2(a * a + b * b, a * b);
                #pragma unroll
                for (int o = 0; o < R; ++o) {
                    int k = j - o;
                    if (k >= 0 && k <= 10) {
                        fma2(accAB[o], WPK(k), ab);
                        fma2(accPQ[o], WPK(k), pq);
                    }
                }
            }
        }

        #pragma unroll
        for (int o = 0; o < R; ++o)
            sV[(g * R + o) * SVS + c] =
                make_float4(accAB[o].x, accAB[o].y, accPQ[o].x, accPQ[o].y);
    }
    __syncthreads();

    // ------- Stage H: j-streaming horizontal 11-tap + SSIM, 6 cols/task ----
    float loss = 0.0f;
    for (int t = tid; t < 9 * TILE_Y; t += NT) {     // 9 chunks x 48 rows = 432
        int row = t % TILE_Y;
        int c0  = (t / TILE_Y) * 6;

        float2 oAB[6], oPQ[6];
        #pragma unroll
        for (int cc = 0; cc < 6; ++cc) {
            oAB[cc] = make_float2(0.f, 0.f);
            oPQ[cc] = make_float2(0.f, 0.f);
        }

        #pragma unroll
        for (int j = 0; j < 16; ++j) {
            float4 v = sV[row * SVS + c0 + j];
            float2 vab = make_float2(v.x, v.y);
            float2 vpq = make_float2(v.z, v.w);
            #pragma unroll
            for (int cc = 0; cc < 6; ++cc) {
                int k = j - cc;
                if (k >= 0 && k <= 10) {
                    fma2(oAB[cc], WPK(k), vab);
                    fma2(oPQ[cc], WPK(k), vpq);
                }
            }
        }

        int  gy  = y0 + row;
        int  ox0 = x0 + c0;
        bool yok = gy < IMG;

        #pragma unroll
        for (int cc = 0; cc < 6; ++cc) {
            float A = oAB[cc].x, B = oAB[cc].y;
            float P = oPQ[cc].x, Q = oPQ[cc].y;
            float AB   = A * B;
            float AA   = A * A;
            float num1 = 2.0f * AB + C1V;
            float num2 = 2.0f * (Q - AB) + C2V;
            float den1 = fmaf(B, B, C1V) + AA;           // AA+BB+C1
            float den2 = (P - den1) + (C1V + C2V);       // P-AA-BB+C2
            float ssim = __fdividef(num1 * num2, den1 * den2);
            float l    = fmaf(ssim, -0.5f, 0.5f);        // (1-ssim)/2
            l = fminf(fmaxf(l, 0.0f), 0.5f);             // clip (NaN-safe)
            if (yok && (ox0 + cc) < IMG) loss += l;
        }
    }

    // ------------- Block reduction + fire-and-forget RED -------------------
    #pragma unroll
    for (int s = 16; s > 0; s >>= 1)
        loss += __shfl_xor_sync(0xFFFFFFFFu, loss, s);

    __shared__ float warpsum[NT / 32];
    if ((tid & 31) == 0) warpsum[tid >> 5] = loss;
    __syncthreads();
    if (tid == 0) {
        float bsum = 0.f;
        #pragma unroll
        for (int w = 0; w < NT / 32; ++w) bsum += warpsum[w];
        atomicAdd(&g_sum, bsum);       // result unused -> REDG, no tail stall
    }
}

extern "C" void kernel_launch(void* const* d_in, const int* in_sizes, int n_in,
                              void* d_out, int out_size)
{
    const float* img1 = (const float*)d_in[0];
    const float* img2 = (const float*)d_in[1];
    float* out = (float*)d_out;

    const int smem_bytes = TILE_Y * SVS * (int)sizeof(float4);  // 49920
    cudaFuncSetAttribute(ssim_main_kernel,
                         cudaFuncAttributeMaxDynamicSharedMemorySize, smem_bytes);

    dim3 grid(GRIDX, GRIDY, 48);   // 10 x 11 x 48 = 5280 blocks
    ssim_main_kernel<<<grid, NT, smem_bytes>>>(img1, img2);
    ssim_finish<<<1, 1>>>(out);
}